// round 14
// baseline (speedup 1.0000x reference)
#include <cuda_runtime.h>
#include <math.h>

// ---------------------------------------------------------------------------
// Model1_11596411699487: 5x 4D conv (valid, stride 1) + ReLU, flatten,
// dense 1280->33 + ReLU, dense 33->2, softmax.
//
// Round 14: R10 build (1485us) + conv2 replaced by y-paired FFMA2 kernel
// (fma.rn.f32x2 over two adjacent y outputs; pair packs hoisted per ky on
// the idle alu pipe). Single-variable probe of the FFMA2 2x fp32 path.
// ---------------------------------------------------------------------------

#define BATCH 256

__device__ float g_h1[BATCH * 3 * 15 * 15 * 15 * 16];  // z-stride padded 15->16
__device__ float g_h2[BATCH * 3 * 12 * 12 * 12 * 12];  // natural stride 12
__device__ float g_h3[BATCH * 4 * 9 * 9 * 9 * 12];     // z-stride padded 9->12
__device__ float g_h4[BATCH * 5 * 6 * 6 * 6 * 8];      // z-stride padded 6->8
__device__ float g_h5[BATCH * 5 * 4 * 4 * 4 * 4];      // exact (feeds head)

typedef unsigned long long u64;

__device__ __forceinline__ u64 pack2(float lo, float hi) {
    u64 r;
    asm("mov.b64 %0, {%1, %2};" : "=l"(r) : "f"(lo), "f"(hi));
    return r;
}
__device__ __forceinline__ void fma2(u64& d, u64 a, u64 b) {
    asm("fma.rn.f32x2 %0, %1, %2, %0;" : "+l"(d) : "l"(a), "l"(b));
}
__device__ __forceinline__ void unpack2(u64 v, float& lo, float& hi) {
    asm("mov.b64 {%0, %1}, %2;" : "=f"(lo), "=f"(hi) : "l"(v));
}

// Exact-length vectorized row load/store. ALIGN = guaranteed alignment (floats).
template <int EXT, int ALIGN>
__device__ __forceinline__ void load_row(float* __restrict__ r,
                                         const float* __restrict__ p)
{
    constexpr int N4 = (ALIGN >= 4) ? EXT / 4 : 0;
    constexpr int R4 = EXT - 4 * N4;
    constexpr int N2 = (ALIGN >= 2) ? R4 / 2 : 0;
    constexpr int N1 = R4 - 2 * N2;
#pragma unroll
    for (int j = 0; j < N4; j++) {
        float4 v = *(const float4*)(p + 4 * j);
        r[4 * j + 0] = v.x; r[4 * j + 1] = v.y;
        r[4 * j + 2] = v.z; r[4 * j + 3] = v.w;
    }
#pragma unroll
    for (int j = 0; j < N2; j++) {
        float2 v = *(const float2*)(p + 4 * N4 + 2 * j);
        r[4 * N4 + 2 * j + 0] = v.x;
        r[4 * N4 + 2 * j + 1] = v.y;
    }
#pragma unroll
    for (int j = 0; j < N1; j++)
        r[4 * N4 + 2 * N2 + j] = p[4 * N4 + 2 * N2 + j];
}

template <int EXT, int ALIGN>
__device__ __forceinline__ void store_row(float* __restrict__ p,
                                          const float* __restrict__ r)
{
    constexpr int N4 = (ALIGN >= 4) ? EXT / 4 : 0;
    constexpr int R4 = EXT - 4 * N4;
    constexpr int N2 = (ALIGN >= 2) ? R4 / 2 : 0;
    constexpr int N1 = R4 - 2 * N2;
#pragma unroll
    for (int j = 0; j < N4; j++) {
        float4 v;
        v.x = r[4 * j + 0]; v.y = r[4 * j + 1];
        v.z = r[4 * j + 2]; v.w = r[4 * j + 3];
        *(float4*)(p + 4 * j) = v;
    }
#pragma unroll
    for (int j = 0; j < N2; j++) {
        float2 v;
        v.x = r[4 * N4 + 2 * j + 0];
        v.y = r[4 * N4 + 2 * j + 1];
        *(float2*)(p + 4 * N4 + 2 * j) = v;
    }
#pragma unroll
    for (int j = 0; j < N1; j++)
        p[4 * N4 + 2 * N2 + j] = r[4 * N4 + 2 * N2 + j];
}

// ---------------------------------------------------------------------------
// Generic spatial conv (R10, verified): conv1/3/4/5.
// ---------------------------------------------------------------------------
template <int Cin, int Cout, int Sin, int K, int COG,
          int PSin, int PSout, int ALIGN, int OALIGN, int WB>
__global__ void __launch_bounds__(128)
conv4d_relu_kernel(const float* __restrict__ in,
                   const float* __restrict__ wt,
                   const float* __restrict__ bias,
                   float* __restrict__ out)
{
    constexpr int Sout = Sin - K + 1;
    constexpr int CPG  = (Cout + COG - 1) / COG;
    constexpr int WSZ  = Cout * Cin * K * K * K * K;
    constexpr int NPOS = Sout * Sout * Sout;

    __shared__ float sw[WSZ];
    __shared__ float sb[Cout];
    for (int i = threadIdx.x; i < WSZ; i += blockDim.x) sw[i] = wt[i];
    if (threadIdx.x < Cout) sb[threadIdx.x] = bias[threadIdx.x];
    __syncthreads();

    int tid = blockIdx.x * blockDim.x + threadIdx.x;
    if (tid >= BATCH * NPOS * COG) return;

    int y0 = tid % Sout;
    int t1 = tid / Sout;
    int x0 = t1 % Sout;
    int t2 = t1 / Sout;
    int w0 = t2 % Sout;
    int t3 = t2 / Sout;
    int b  = t3 % BATCH;
    int g  = t3 / BATCH;
    int co0 = g * CPG;

    float acc[CPG * Sout];
#pragma unroll
    for (int c = 0; c < CPG; c++) {
        float bv = (co0 + c < Cout) ? sb[co0 + c] : 0.0f;
#pragma unroll
        for (int z = 0; z < Sout; z++) acc[c * Sout + z] = bv;
    }

#pragma unroll 1
    for (int ci = 0; ci < Cin; ci++) {
#pragma unroll 1
        for (int kw = 0; kw < K; kw++) {
#pragma unroll 1
            for (int kx = 0; kx < K; kx++) {
                const float* base = in +
                    (size_t)((((b * Cin + ci) * Sin + (w0 + kw)) * Sin + (x0 + kx)) * Sin
                             + y0) * PSin;
                float r[K][Sin];
#pragma unroll
                for (int ky = 0; ky < K; ky++)
                    load_row<Sin, ALIGN>(r[ky], base + ky * PSin);

#pragma unroll
                for (int ky = 0; ky < K; ky++) {
                    if (WB) {
                        float wv[CPG * K];
#pragma unroll
                        for (int c = 0; c < CPG; c++) {
                            int co = co0 + c;
                            if (co >= Cout) break;
#pragma unroll
                            for (int kz = 0; kz < K; kz++)
                                wv[c * K + kz] =
                                    sw[((((co * Cin + ci) * K + kw) * K + kx) * K + ky) * K + kz];
                        }
#pragma unroll
                        for (int c = 0; c < CPG; c++) {
                            int co = co0 + c;
                            if (co >= Cout) break;
#pragma unroll
                            for (int kz = 0; kz < K; kz++) {
                                float w = wv[c * K + kz];
#pragma unroll
                                for (int z = 0; z < Sout; z++)
                                    acc[c * Sout + z] += r[ky][z + kz] * w;
                            }
                        }
                    } else {
#pragma unroll
                        for (int c = 0; c < CPG; c++) {
                            int co = co0 + c;
                            if (co >= Cout) break;
#pragma unroll
                            for (int kz = 0; kz < K; kz++) {
                                float w = sw[((((co * Cin + ci) * K + kw) * K + kx) * K + ky) * K + kz];
#pragma unroll
                                for (int z = 0; z < Sout; z++)
                                    acc[c * Sout + z] += r[ky][z + kz] * w;
                            }
                        }
                    }
                }
            }
        }
    }

#pragma unroll
    for (int c = 0; c < CPG; c++) {
        int co = co0 + c;
        if (co >= Cout) break;
        float* op = out +
            (size_t)((((b * Cout + co) * Sout + w0) * Sout + x0) * Sout + y0) * PSout;
        float rr[Sout];
#pragma unroll
        for (int z = 0; z < Sout; z++) rr[z] = fmaxf(acc[c * Sout + z], 0.0f);
        store_row<Sout, OALIGN>(op, rr);
    }
}

// ---------------------------------------------------------------------------
// conv2 y-paired FFMA2 kernel: 3->3, 15->12, k=4, in h1 (z-stride 16),
// out h2 (natural stride 12).
// Thread owns (co, b, w0, x0, y-pair): two adjacent y outputs, all 12 z,
// in packed f32x2 accumulators. Pair operands packed once per ky.
// ---------------------------------------------------------------------------
__global__ void __launch_bounds__(128)
conv2_ypair_kernel(const float* __restrict__ in,
                   const float* __restrict__ wt,
                   const float* __restrict__ bias,
                   float* __restrict__ out)
{
    constexpr int Cin = 3, Cout = 3, Sin = 15, K = 4, Sout = 12, PSin = 16;
    constexpr int YP  = Sout / 2;                  // 6 y-pairs
    constexpr int WSZ = Cout * Cin * K * K * K * K;

    __shared__ float sw[WSZ];
    __shared__ float sb[Cout];
    for (int i = threadIdx.x; i < WSZ; i += blockDim.x) sw[i] = wt[i];
    if (threadIdx.x < Cout) sb[threadIdx.x] = bias[threadIdx.x];
    __syncthreads();

    int tid = blockIdx.x * 128 + threadIdx.x;
    if (tid >= BATCH * Sout * Sout * YP * Cout) return;

    int yp = tid % YP;
    int t1 = tid / YP;
    int x0 = t1 % Sout;
    int t2 = t1 / Sout;
    int w0 = t2 % Sout;
    int t3 = t2 / Sout;
    int b  = t3 % BATCH;
    int co = t3 / BATCH;
    int y0 = yp * 2;

    u64 acc2[Sout];
    {
        float bv = sb[co];
        u64 bp = pack2(bv, bv);
#pragma unroll
        for (int z = 0; z < Sout; z++) acc2[z] = bp;
    }

#pragma unroll 1
    for (int ci = 0; ci < Cin; ci++) {
#pragma unroll 1
        for (int kw = 0; kw < K; kw++) {
#pragma unroll 1
            for (int kx = 0; kx < K; kx++) {
                const float* base = in +
                    (size_t)((((b * Cin + ci) * Sin + (w0 + kw)) * Sin + (x0 + kx)) * Sin
                             + y0) * PSin;
                // rows y0 .. y0+4 (5 rows serve ky and ky+1 pairing)
                float r[K + 1][Sin];
#pragma unroll
                for (int j = 0; j <= K; j++)
                    load_row<Sin, 4>(r[j], base + j * PSin);

#pragma unroll
                for (int ky = 0; ky < K; ky++) {
                    // pair rows: {in(y0+ky, z), in(y0+1+ky, z)}
                    u64 pr[Sin];
#pragma unroll
                    for (int z = 0; z < Sin; z++)
                        pr[z] = pack2(r[ky][z], r[ky + 1][z]);
#pragma unroll
                    for (int kz = 0; kz < K; kz++) {
                        float w = sw[((((co * Cin + ci) * K + kw) * K + kx) * K + ky) * K + kz];
                        u64 w2 = pack2(w, w);
#pragma unroll
                        for (int z = 0; z < Sout; z++)
                            fma2(acc2[z], pr[z + kz], w2);
                    }
                }
            }
        }
    }

    float lo[Sout], hi[Sout];
#pragma unroll
    for (int z = 0; z < Sout; z++) {
        float l, h;
        unpack2(acc2[z], l, h);
        lo[z] = fmaxf(l, 0.0f);
        hi[z] = fmaxf(h, 0.0f);
    }
    float* op = out +
        (size_t)((((b * Cout + co) * Sout + w0) * Sout + x0) * Sout + y0) * Sout;
    store_row<Sout, 4>(op, lo);
    store_row<Sout, 4>(op + Sout, hi);
}

// ---------------------------------------------------------------------------
// Head: per-sample block. dense 1280->33 (ReLU), dense 33->2, softmax.
// ---------------------------------------------------------------------------
__global__ void __launch_bounds__(64)
head_kernel(const float* __restrict__ h,
            const float* __restrict__ dw1, const float* __restrict__ db1,
            const float* __restrict__ dw2, const float* __restrict__ db2,
            float* __restrict__ out)
{
    int b = blockIdx.x;
    __shared__ float sh[1280];
    __shared__ float s1[33];

    for (int i = threadIdx.x; i < 1280; i += blockDim.x)
        sh[i] = h[b * 1280 + i];
    __syncthreads();

    int j = threadIdx.x;
    if (j < 33) {
        float s = db1[j];
        const float* wr = dw1 + j * 1280;
#pragma unroll 4
        for (int i = 0; i < 1280; i++) s += wr[i] * sh[i];
        s1[j] = fmaxf(s, 0.0f);
    }
    __syncthreads();

    if (threadIdx.x == 0) {
        float l0 = db2[0], l1 = db2[1];
        for (int jj = 0; jj < 33; jj++) {
            l0 += dw2[jj] * s1[jj];
            l1 += dw2[33 + jj] * s1[jj];
        }
        float m  = fmaxf(l0, l1);
        float e0 = expf(l0 - m);
        float e1 = expf(l1 - m);
        float inv = 1.0f / (e0 + e1);
        out[b * 2 + 0] = e0 * inv;
        out[b * 2 + 1] = e1 * inv;
    }
}

static inline int cdiv(int a, int b) { return (a + b - 1) / b; }

extern "C" void kernel_launch(void* const* d_in, const int* in_sizes, int n_in,
                              void* d_out, int out_size)
{
    const float* x   = (const float*)d_in[0];
    const float* w1  = (const float*)d_in[1];
    const float* b1  = (const float*)d_in[2];
    const float* w2  = (const float*)d_in[3];
    const float* b2  = (const float*)d_in[4];
    const float* w3  = (const float*)d_in[5];
    const float* b3  = (const float*)d_in[6];
    const float* w4  = (const float*)d_in[7];
    const float* b4  = (const float*)d_in[8];
    const float* w5  = (const float*)d_in[9];
    const float* b5  = (const float*)d_in[10];
    const float* dw1 = (const float*)d_in[11];
    const float* db1 = (const float*)d_in[12];
    const float* dw2 = (const float*)d_in[13];
    const float* db2 = (const float*)d_in[14];
    float* out = (float*)d_out;

    float *h1, *h2, *h3, *h4, *h5;
    cudaGetSymbolAddress((void**)&h1, g_h1);
    cudaGetSymbolAddress((void**)&h2, g_h2);
    cudaGetSymbolAddress((void**)&h3, g_h3);
    cudaGetSymbolAddress((void**)&h4, g_h4);
    cudaGetSymbolAddress((void**)&h5, g_h5);

    const int T = 128;

    // conv1: 1->3, 18->15, k=4. float2 in (x stride 18), out h1 stride 16.
    conv4d_relu_kernel<1, 3, 18, 4, 1, 18, 16, 2, 4, 0>
        <<<cdiv(BATCH * 15 * 15 * 15, T), T>>>(x, w1, b1, h1);
    // conv2: 3->3, 15->12, k=4. y-paired FFMA2 probe kernel.
    {
        int threads = BATCH * 12 * 12 * 6 * 3;
        conv2_ypair_kernel<<<cdiv(threads, T), T>>>(h1, w2, b2, h2);
    }
    // conv3: 3->4, 12->9, k=4. float4 reads h2 (stride 12), out h3 stride 12.
    conv4d_relu_kernel<3, 4, 12, 4, 1, 12, 12, 4, 4, 1>
        <<<cdiv(BATCH * 9 * 9 * 9, T), T>>>(h2, w3, b3, h3);
    // conv4: 4->5, 9->6, k=4. float4 reads h3 (stride 12), co split x2,
    // out h4 stride 8.
    conv4d_relu_kernel<4, 5, 9, 4, 2, 12, 8, 4, 4, 1>
        <<<cdiv(BATCH * 6 * 6 * 6 * 2, T), T>>>(h3, w4, b4, h4);
    // conv5: 5->5, 6->4, k=3. float4 reads h4 (stride 8), co split x5, out exact.
    conv4d_relu_kernel<5, 5, 6, 3, 5, 8, 4, 4, 4, 1>
        <<<cdiv(BATCH * 4 * 4 * 4 * 5, T), T>>>(h4, w5, b5, h5);
    // head
    head_kernel<<<BATCH, 64>>>(h5, dw1, db1, dw2, db2, out);
}

// round 15
// speedup vs baseline: 1.0129x; 1.0129x over previous
#include <cuda_runtime.h>
#include <math.h>

// ---------------------------------------------------------------------------
// Model1_11596411699487: 5x 4D conv (valid, stride 1) + ReLU, flatten,
// dense 1280->33 + ReLU, dense 33->2, softmax.
//
// Round 15: conv1/2/3 use SMEM plane staging — block owns (b,w0), stages one
// (ci,kw) input plane into padded SMEM (stride 20 -> conflict-free LDS.128),
// threads (x0,y0) consume it. conv4/conv5/head = verified R10 kernels.
// ---------------------------------------------------------------------------

#define BATCH 256

__device__ float g_h1[BATCH * 3 * 15 * 15 * 15 * 16];  // z-stride padded 15->16
__device__ float g_h2[BATCH * 3 * 12 * 12 * 12 * 12];  // natural stride 12
__device__ float g_h3[BATCH * 4 * 9 * 9 * 9 * 12];     // z-stride padded 9->12
__device__ float g_h4[BATCH * 5 * 6 * 6 * 6 * 8];      // z-stride padded 6->8
__device__ float g_h5[BATCH * 5 * 4 * 4 * 4 * 4];      // exact (feeds head)

// Exact-length vectorized row load/store. ALIGN = guaranteed alignment (floats).
template <int EXT, int ALIGN>
__device__ __forceinline__ void load_row(float* __restrict__ r,
                                         const float* __restrict__ p)
{
    constexpr int N4 = (ALIGN >= 4) ? EXT / 4 : 0;
    constexpr int R4 = EXT - 4 * N4;
    constexpr int N2 = (ALIGN >= 2) ? R4 / 2 : 0;
    constexpr int N1 = R4 - 2 * N2;
#pragma unroll
    for (int j = 0; j < N4; j++) {
        float4 v = *(const float4*)(p + 4 * j);
        r[4 * j + 0] = v.x; r[4 * j + 1] = v.y;
        r[4 * j + 2] = v.z; r[4 * j + 3] = v.w;
    }
#pragma unroll
    for (int j = 0; j < N2; j++) {
        float2 v = *(const float2*)(p + 4 * N4 + 2 * j);
        r[4 * N4 + 2 * j + 0] = v.x;
        r[4 * N4 + 2 * j + 1] = v.y;
    }
#pragma unroll
    for (int j = 0; j < N1; j++)
        r[4 * N4 + 2 * N2 + j] = p[4 * N4 + 2 * N2 + j];
}

template <int EXT, int ALIGN>
__device__ __forceinline__ void store_row(float* __restrict__ p,
                                          const float* __restrict__ r)
{
    constexpr int N4 = (ALIGN >= 4) ? EXT / 4 : 0;
    constexpr int R4 = EXT - 4 * N4;
    constexpr int N2 = (ALIGN >= 2) ? R4 / 2 : 0;
    constexpr int N1 = R4 - 2 * N2;
#pragma unroll
    for (int j = 0; j < N4; j++) {
        float4 v;
        v.x = r[4 * j + 0]; v.y = r[4 * j + 1];
        v.z = r[4 * j + 2]; v.w = r[4 * j + 3];
        *(float4*)(p + 4 * j) = v;
    }
#pragma unroll
    for (int j = 0; j < N2; j++) {
        float2 v;
        v.x = r[4 * N4 + 2 * j + 0];
        v.y = r[4 * N4 + 2 * j + 1];
        *(float2*)(p + 4 * N4 + 2 * j) = v;
    }
#pragma unroll
    for (int j = 0; j < N1; j++)
        p[4 * N4 + 2 * N2 + j] = r[4 * N4 + 2 * N2 + j];
}

// ---------------------------------------------------------------------------
// SMEM-staged conv: block = (b, w0). Per (ci,kw): cooperatively stage the
// input plane (x,y,z) for w = w0+kw into SMEM (z-stride SPAD=20, conflict-
// free for stride-20 LDS.128 lane patterns), then threads (x0,y0) run the
// dense FFMA block from SMEM rows.
//   PSin/PSout: gmem z-strides. NT: block size (>= Sout*Sout).
// ---------------------------------------------------------------------------
template <int Cin, int Cout, int Sin, int K,
          int PSin, int PSout, int OALIGN, int NT>
__global__ void __launch_bounds__(NT)
conv4d_smem_kernel(const float* __restrict__ in,
                   const float* __restrict__ wt,
                   const float* __restrict__ bias,
                   float* __restrict__ out)
{
    constexpr int Sout  = Sin - K + 1;
    constexpr int SPAD  = 20;                 // smem z-stride (floats)
    constexpr int PLANE = Sin * Sin;          // rows per plane
    constexpr int WSZ   = Cout * Cin * K * K * K * K;
    static_assert(NT >= Sout * Sout, "block must cover (x0,y0)");
    static_assert(PSin % 2 == 0, "copy vector width");

    __shared__ float sp[PLANE * SPAD];
    __shared__ float sw[WSZ];
    __shared__ float sb[Cout];

    int tid = threadIdx.x;
    for (int i = tid; i < WSZ; i += NT) sw[i] = wt[i];
    if (tid < Cout) sb[tid] = bias[tid];

    int b  = blockIdx.x / Sout;
    int w0 = blockIdx.x % Sout;

    bool active = tid < Sout * Sout;
    int x0 = tid / Sout;
    int y0 = tid % Sout;

    float acc[Cout * Sout];
#pragma unroll
    for (int c = 0; c < Cout; c++)
#pragma unroll
        for (int z = 0; z < Sout; z++) acc[c * Sout + z] = 0.0f;

#pragma unroll 1
    for (int ci = 0; ci < Cin; ci++) {
#pragma unroll 1
        for (int kw = 0; kw < K; kw++) {
            __syncthreads();   // previous iteration's reads done
            // ---- stage plane (b, ci, w0+kw) ----
            const float* gp = in +
                (size_t)(((b * Cin + ci) * Sin + (w0 + kw)) * PLANE) * PSin;
            if ((PSin & 3) == 0) {
                constexpr int V = PSin / 4;   // float4 per row
                const float4* g4 = (const float4*)gp;
                for (int v = tid; v < PLANE * V; v += NT) {
                    int row = v / V, j = v % V;
                    float4 val = g4[v];
                    *(float4*)&sp[row * SPAD + j * 4] = val;
                }
            } else {
                constexpr int V = PSin / 2;   // float2 per row
                const float2* g2 = (const float2*)gp;
                for (int v = tid; v < PLANE * V; v += NT) {
                    int row = v / V, j = v % V;
                    float2 val = g2[v];
                    *(float2*)&sp[row * SPAD + j * 2] = val;
                }
            }
            __syncthreads();

            // ---- consume plane ----
            if (active) {
#pragma unroll
                for (int kx = 0; kx < K; kx++) {
#pragma unroll
                    for (int ky = 0; ky < K; ky++) {
                        const float* rp = &sp[((x0 + kx) * Sin + (y0 + ky)) * SPAD];
                        float r[Sin];
                        load_row<Sin, 4>(r, rp);
#pragma unroll
                        for (int c = 0; c < Cout; c++) {
#pragma unroll
                            for (int kz = 0; kz < K; kz++) {
                                float w = sw[((((c * Cin + ci) * K + kw) * K + kx) * K + ky) * K + kz];
#pragma unroll
                                for (int z = 0; z < Sout; z++)
                                    acc[c * Sout + z] += r[z + kz] * w;
                            }
                        }
                    }
                }
            }
        }
    }

    if (active) {
#pragma unroll
        for (int c = 0; c < Cout; c++) {
            float* op = out +
                (size_t)((((b * Cout + c) * Sout + w0) * Sout + x0) * Sout + y0) * PSout;
            float rr[Sout];
#pragma unroll
            for (int z = 0; z < Sout; z++)
                rr[z] = fmaxf(acc[c * Sout + z] + sb[c], 0.0f);
            store_row<Sout, OALIGN>(op, rr);
        }
    }
}

// ---------------------------------------------------------------------------
// R10 direct conv (verified): conv4/conv5.
// ---------------------------------------------------------------------------
template <int Cin, int Cout, int Sin, int K, int COG,
          int PSin, int PSout, int ALIGN, int OALIGN>
__global__ void __launch_bounds__(128)
conv4d_relu_kernel(const float* __restrict__ in,
                   const float* __restrict__ wt,
                   const float* __restrict__ bias,
                   float* __restrict__ out)
{
    constexpr int Sout = Sin - K + 1;
    constexpr int CPG  = (Cout + COG - 1) / COG;
    constexpr int WSZ  = Cout * Cin * K * K * K * K;
    constexpr int NPOS = Sout * Sout * Sout;

    __shared__ float sw[WSZ];
    __shared__ float sb[Cout];
    for (int i = threadIdx.x; i < WSZ; i += blockDim.x) sw[i] = wt[i];
    if (threadIdx.x < Cout) sb[threadIdx.x] = bias[threadIdx.x];
    __syncthreads();

    int tid = blockIdx.x * blockDim.x + threadIdx.x;
    if (tid >= BATCH * NPOS * COG) return;

    int y0 = tid % Sout;
    int t1 = tid / Sout;
    int x0 = t1 % Sout;
    int t2 = t1 / Sout;
    int w0 = t2 % Sout;
    int t3 = t2 / Sout;
    int b  = t3 % BATCH;
    int g  = t3 / BATCH;
    int co0 = g * CPG;

    float acc[CPG * Sout];
#pragma unroll
    for (int c = 0; c < CPG; c++) {
        float bv = (co0 + c < Cout) ? sb[co0 + c] : 0.0f;
#pragma unroll
        for (int z = 0; z < Sout; z++) acc[c * Sout + z] = bv;
    }

#pragma unroll 1
    for (int ci = 0; ci < Cin; ci++) {
#pragma unroll 1
        for (int kw = 0; kw < K; kw++) {
#pragma unroll 1
            for (int kx = 0; kx < K; kx++) {
                const float* base = in +
                    (size_t)((((b * Cin + ci) * Sin + (w0 + kw)) * Sin + (x0 + kx)) * Sin
                             + y0) * PSin;
                float r[K][Sin];
#pragma unroll
                for (int ky = 0; ky < K; ky++)
                    load_row<Sin, ALIGN>(r[ky], base + ky * PSin);

#pragma unroll
                for (int ky = 0; ky < K; ky++) {
                    float wv[CPG * K];
#pragma unroll
                    for (int c = 0; c < CPG; c++) {
                        int co = co0 + c;
                        if (co >= Cout) break;
#pragma unroll
                        for (int kz = 0; kz < K; kz++)
                            wv[c * K + kz] =
                                sw[((((co * Cin + ci) * K + kw) * K + kx) * K + ky) * K + kz];
                    }
#pragma unroll
                    for (int c = 0; c < CPG; c++) {
                        int co = co0 + c;
                        if (co >= Cout) break;
#pragma unroll
                        for (int kz = 0; kz < K; kz++) {
                            float w = wv[c * K + kz];
#pragma unroll
                            for (int z = 0; z < Sout; z++)
                                acc[c * Sout + z] += r[ky][z + kz] * w;
                        }
                    }
                }
            }
        }
    }

#pragma unroll
    for (int c = 0; c < CPG; c++) {
        int co = co0 + c;
        if (co >= Cout) break;
        float* op = out +
            (size_t)((((b * Cout + co) * Sout + w0) * Sout + x0) * Sout + y0) * PSout;
        float rr[Sout];
#pragma unroll
        for (int z = 0; z < Sout; z++) rr[z] = fmaxf(acc[c * Sout + z], 0.0f);
        store_row<Sout, OALIGN>(op, rr);
    }
}

// ---------------------------------------------------------------------------
// Head: per-sample block. dense 1280->33 (ReLU), dense 33->2, softmax.
// ---------------------------------------------------------------------------
__global__ void __launch_bounds__(64)
head_kernel(const float* __restrict__ h,
            const float* __restrict__ dw1, const float* __restrict__ db1,
            const float* __restrict__ dw2, const float* __restrict__ db2,
            float* __restrict__ out)
{
    int b = blockIdx.x;
    __shared__ float sh[1280];
    __shared__ float s1[33];

    for (int i = threadIdx.x; i < 1280; i += blockDim.x)
        sh[i] = h[b * 1280 + i];
    __syncthreads();

    int j = threadIdx.x;
    if (j < 33) {
        float s = db1[j];
        const float* wr = dw1 + j * 1280;
#pragma unroll 4
        for (int i = 0; i < 1280; i++) s += wr[i] * sh[i];
        s1[j] = fmaxf(s, 0.0f);
    }
    __syncthreads();

    if (threadIdx.x == 0) {
        float l0 = db2[0], l1 = db2[1];
        for (int jj = 0; jj < 33; jj++) {
            l0 += dw2[jj] * s1[jj];
            l1 += dw2[33 + jj] * s1[jj];
        }
        float m  = fmaxf(l0, l1);
        float e0 = expf(l0 - m);
        float e1 = expf(l1 - m);
        float inv = 1.0f / (e0 + e1);
        out[b * 2 + 0] = e0 * inv;
        out[b * 2 + 1] = e1 * inv;
    }
}

static inline int cdiv(int a, int b) { return (a + b - 1) / b; }

extern "C" void kernel_launch(void* const* d_in, const int* in_sizes, int n_in,
                              void* d_out, int out_size)
{
    const float* x   = (const float*)d_in[0];
    const float* w1  = (const float*)d_in[1];
    const float* b1  = (const float*)d_in[2];
    const float* w2  = (const float*)d_in[3];
    const float* b2  = (const float*)d_in[4];
    const float* w3  = (const float*)d_in[5];
    const float* b3  = (const float*)d_in[6];
    const float* w4  = (const float*)d_in[7];
    const float* b4  = (const float*)d_in[8];
    const float* w5  = (const float*)d_in[9];
    const float* b5  = (const float*)d_in[10];
    const float* dw1 = (const float*)d_in[11];
    const float* db1 = (const float*)d_in[12];
    const float* dw2 = (const float*)d_in[13];
    const float* db2 = (const float*)d_in[14];
    float* out = (float*)d_out;

    float *h1, *h2, *h3, *h4, *h5;
    cudaGetSymbolAddress((void**)&h1, g_h1);
    cudaGetSymbolAddress((void**)&h2, g_h2);
    cudaGetSymbolAddress((void**)&h3, g_h3);
    cudaGetSymbolAddress((void**)&h4, g_h4);
    cudaGetSymbolAddress((void**)&h5, g_h5);

    // conv1: 1->3, 18->15, k=4. SMEM-staged; x z-stride 18 (float2 copy),
    // out h1 stride 16. Block = (b,w0): 225 active of 256.
    conv4d_smem_kernel<1, 3, 18, 4, 18, 16, 4, 256>
        <<<BATCH * 15, 256>>>(x, w1, b1, h1);
    // conv2: 3->3, 15->12, k=4. SMEM-staged; h1 z-stride 16 (float4 copy),
    // out h2 stride 12. Block = (b,w0): 144 active of 160.
    conv4d_smem_kernel<3, 3, 15, 4, 16, 12, 4, 160>
        <<<BATCH * 12, 160>>>(h1, w2, b2, h2);
    // conv3: 3->4, 12->9, k=4. SMEM-staged; h2 z-stride 12 (float4 copy),
    // out h3 stride 12. Block = (b,w0): 81 active of 96.
    conv4d_smem_kernel<3, 4, 12, 4, 12, 12, 4, 96>
        <<<BATCH * 9, 96>>>(h2, w3, b3, h3);
    // conv4: 4->5, 9->6, k=4. R10 direct (verified, 108us).
    conv4d_relu_kernel<4, 5, 9, 4, 2, 12, 8, 4, 4>
        <<<cdiv(BATCH * 6 * 6 * 6 * 2, 128), 128>>>(h3, w4, b4, h4);
    // conv5: 5->5, 6->4, k=3. R10 direct.
    conv4d_relu_kernel<5, 5, 6, 3, 5, 8, 4, 4, 4>
        <<<cdiv(BATCH * 4 * 4 * 4 * 5, 128), 128>>>(h4, w5, b5, h5);
    // head
    head_kernel<<<BATCH, 64>>>(h5, dw1, db1, dw2, db2, out);
}

// round 16
// speedup vs baseline: 1.6741x; 1.6528x over previous
#include <cuda_runtime.h>
#include <math.h>

// ---------------------------------------------------------------------------
// Model1_11596411699487: 5x 4D conv (valid, stride 1) + ReLU, flatten,
// dense 1280->33 + ReLU, dense 33->2, softmax.
//
// Round 16: R10 build (1485us best) with conv2 replaced by an x-tiled (TX=2)
// kernel: each thread computes 2 adjacent x outputs, reusing every loaded
// input row across all (t,kx) pairs -> 1.6x fewer L1 wavefronts.
// ---------------------------------------------------------------------------

#define BATCH 256

__device__ float g_h1[BATCH * 3 * 15 * 15 * 15 * 16];  // z-stride padded 15->16
__device__ float g_h2[BATCH * 3 * 12 * 12 * 12 * 12];  // natural stride 12
__device__ float g_h3[BATCH * 4 * 9 * 9 * 9 * 12];     // z-stride padded 9->12
__device__ float g_h4[BATCH * 5 * 6 * 6 * 6 * 8];      // z-stride padded 6->8
__device__ float g_h5[BATCH * 5 * 4 * 4 * 4 * 4];      // exact (feeds head)

// Exact-length vectorized row load/store. ALIGN = guaranteed alignment (floats).
template <int EXT, int ALIGN>
__device__ __forceinline__ void load_row(float* __restrict__ r,
                                         const float* __restrict__ p)
{
    constexpr int N4 = (ALIGN >= 4) ? EXT / 4 : 0;
    constexpr int R4 = EXT - 4 * N4;
    constexpr int N2 = (ALIGN >= 2) ? R4 / 2 : 0;
    constexpr int N1 = R4 - 2 * N2;
#pragma unroll
    for (int j = 0; j < N4; j++) {
        float4 v = *(const float4*)(p + 4 * j);
        r[4 * j + 0] = v.x; r[4 * j + 1] = v.y;
        r[4 * j + 2] = v.z; r[4 * j + 3] = v.w;
    }
#pragma unroll
    for (int j = 0; j < N2; j++) {
        float2 v = *(const float2*)(p + 4 * N4 + 2 * j);
        r[4 * N4 + 2 * j + 0] = v.x;
        r[4 * N4 + 2 * j + 1] = v.y;
    }
#pragma unroll
    for (int j = 0; j < N1; j++)
        r[4 * N4 + 2 * N2 + j] = p[4 * N4 + 2 * N2 + j];
}

template <int EXT, int ALIGN>
__device__ __forceinline__ void store_row(float* __restrict__ p,
                                          const float* __restrict__ r)
{
    constexpr int N4 = (ALIGN >= 4) ? EXT / 4 : 0;
    constexpr int R4 = EXT - 4 * N4;
    constexpr int N2 = (ALIGN >= 2) ? R4 / 2 : 0;
    constexpr int N1 = R4 - 2 * N2;
#pragma unroll
    for (int j = 0; j < N4; j++) {
        float4 v;
        v.x = r[4 * j + 0]; v.y = r[4 * j + 1];
        v.z = r[4 * j + 2]; v.w = r[4 * j + 3];
        *(float4*)(p + 4 * j) = v;
    }
#pragma unroll
    for (int j = 0; j < N2; j++) {
        float2 v;
        v.x = r[4 * N4 + 2 * j + 0];
        v.y = r[4 * N4 + 2 * j + 1];
        *(float2*)(p + 4 * N4 + 2 * j) = v;
    }
#pragma unroll
    for (int j = 0; j < N1; j++)
        p[4 * N4 + 2 * N2 + j] = r[4 * N4 + 2 * N2 + j];
}

// ---------------------------------------------------------------------------
// R10 direct conv (verified): conv1/3/4/5.
// ---------------------------------------------------------------------------
template <int Cin, int Cout, int Sin, int K, int COG,
          int PSin, int PSout, int ALIGN, int OALIGN, int WB>
__global__ void __launch_bounds__(128)
conv4d_relu_kernel(const float* __restrict__ in,
                   const float* __restrict__ wt,
                   const float* __restrict__ bias,
                   float* __restrict__ out)
{
    constexpr int Sout = Sin - K + 1;
    constexpr int CPG  = (Cout + COG - 1) / COG;
    constexpr int WSZ  = Cout * Cin * K * K * K * K;
    constexpr int NPOS = Sout * Sout * Sout;

    __shared__ float sw[WSZ];
    __shared__ float sb[Cout];
    for (int i = threadIdx.x; i < WSZ; i += blockDim.x) sw[i] = wt[i];
    if (threadIdx.x < Cout) sb[threadIdx.x] = bias[threadIdx.x];
    __syncthreads();

    int tid = blockIdx.x * blockDim.x + threadIdx.x;
    if (tid >= BATCH * NPOS * COG) return;

    int y0 = tid % Sout;
    int t1 = tid / Sout;
    int x0 = t1 % Sout;
    int t2 = t1 / Sout;
    int w0 = t2 % Sout;
    int t3 = t2 / Sout;
    int b  = t3 % BATCH;
    int g  = t3 / BATCH;
    int co0 = g * CPG;

    float acc[CPG * Sout];
#pragma unroll
    for (int c = 0; c < CPG; c++) {
        float bv = (co0 + c < Cout) ? sb[co0 + c] : 0.0f;
#pragma unroll
        for (int z = 0; z < Sout; z++) acc[c * Sout + z] = bv;
    }

#pragma unroll 1
    for (int ci = 0; ci < Cin; ci++) {
#pragma unroll 1
        for (int kw = 0; kw < K; kw++) {
#pragma unroll 1
            for (int kx = 0; kx < K; kx++) {
                const float* base = in +
                    (size_t)((((b * Cin + ci) * Sin + (w0 + kw)) * Sin + (x0 + kx)) * Sin
                             + y0) * PSin;
                float r[K][Sin];
#pragma unroll
                for (int ky = 0; ky < K; ky++)
                    load_row<Sin, ALIGN>(r[ky], base + ky * PSin);

#pragma unroll
                for (int ky = 0; ky < K; ky++) {
                    if (WB) {
                        float wv[CPG * K];
#pragma unroll
                        for (int c = 0; c < CPG; c++) {
                            int co = co0 + c;
                            if (co >= Cout) break;
#pragma unroll
                            for (int kz = 0; kz < K; kz++)
                                wv[c * K + kz] =
                                    sw[((((co * Cin + ci) * K + kw) * K + kx) * K + ky) * K + kz];
                        }
#pragma unroll
                        for (int c = 0; c < CPG; c++) {
                            int co = co0 + c;
                            if (co >= Cout) break;
#pragma unroll
                            for (int kz = 0; kz < K; kz++) {
                                float w = wv[c * K + kz];
#pragma unroll
                                for (int z = 0; z < Sout; z++)
                                    acc[c * Sout + z] += r[ky][z + kz] * w;
                            }
                        }
                    } else {
#pragma unroll
                        for (int c = 0; c < CPG; c++) {
                            int co = co0 + c;
                            if (co >= Cout) break;
#pragma unroll
                            for (int kz = 0; kz < K; kz++) {
                                float w = sw[((((co * Cin + ci) * K + kw) * K + kx) * K + ky) * K + kz];
#pragma unroll
                                for (int z = 0; z < Sout; z++)
                                    acc[c * Sout + z] += r[ky][z + kz] * w;
                            }
                        }
                    }
                }
            }
        }
    }

#pragma unroll
    for (int c = 0; c < CPG; c++) {
        int co = co0 + c;
        if (co >= Cout) break;
        float* op = out +
            (size_t)((((b * Cout + co) * Sout + w0) * Sout + x0) * Sout + y0) * PSout;
        float rr[Sout];
#pragma unroll
        for (int z = 0; z < Sout; z++) rr[z] = fmaxf(acc[c * Sout + z], 0.0f);
        store_row<Sout, OALIGN>(op, rr);
    }
}

// ---------------------------------------------------------------------------
// conv2 x-tiled kernel (TX=2): 3->3, 15->12, k=4; in h1 (z-stride 16),
// out h2 (stride 12).
// Thread owns (b, w0, x-tile, y0): outputs (x0, x0+1) x 12 z x 3 co.
// Per (ci,kw): loop xr = 0..4 (x = x0+xr); the 4 ky rows at that x feed all
// (t,kx) pairs with t+kx == xr. 80 LDG per (ci,kw) for 2 outputs vs 128.
// xr/kx fully unrolled so acc[] indexing stays static.
// ---------------------------------------------------------------------------
__global__ void __launch_bounds__(128)
conv2_tx2_kernel(const float* __restrict__ in,
                 const float* __restrict__ wt,
                 const float* __restrict__ bias,
                 float* __restrict__ out)
{
    constexpr int Cin = 3, Cout = 3, Sin = 15, K = 4, Sout = 12;
    constexpr int PSin = 16, PSout = 12;
    constexpr int TX = 2;
    constexpr int XT = Sout / TX;               // 6 x-tiles
    constexpr int WSZ = Cout * Cin * K * K * K * K;

    __shared__ float sw[WSZ];
    __shared__ float sb[Cout];
    for (int i = threadIdx.x; i < WSZ; i += blockDim.x) sw[i] = wt[i];
    if (threadIdx.x < Cout) sb[threadIdx.x] = bias[threadIdx.x];
    __syncthreads();

    int tid = blockIdx.x * 128 + threadIdx.x;
    if (tid >= BATCH * Sout * XT * Sout) return;

    int y0 = tid % Sout;
    int t1 = tid / Sout;
    int xt = t1 % XT;
    int t2 = t1 / XT;
    int w0 = t2 % Sout;
    int b  = t2 / Sout;
    int x0 = xt * TX;

    float acc[Cout * TX * Sout];   // 72 accumulators
#pragma unroll
    for (int co = 0; co < Cout; co++) {
        float bv = sb[co];
#pragma unroll
        for (int t = 0; t < TX; t++)
#pragma unroll
            for (int z = 0; z < Sout; z++)
                acc[(co * TX + t) * Sout + z] = bv;
    }

#pragma unroll 1
    for (int ci = 0; ci < Cin; ci++) {
#pragma unroll 1
        for (int kw = 0; kw < K; kw++) {
            const float* kwbase = in +
                (size_t)(((b * Cin + ci) * Sin + (w0 + kw)) * Sin) * Sin * PSin;
#pragma unroll
            for (int xr = 0; xr < TX + K - 1; xr++) {   // 5 x rows
                const float* base = kwbase +
                    (size_t)((x0 + xr) * Sin + y0) * PSin;
                // ky rows in pairs to bound register pressure
#pragma unroll
                for (int kh = 0; kh < K / 2; kh++) {
                    float r[2][Sin];
                    load_row<Sin, 4>(r[0], base + (2 * kh + 0) * PSin);
                    load_row<Sin, 4>(r[1], base + (2 * kh + 1) * PSin);
#pragma unroll
                    for (int j = 0; j < 2; j++) {
                        const int ky = 2 * kh + j;
#pragma unroll
                        for (int kx = 0; kx < K; kx++) {
                            const int t = xr - kx;          // compile-time
                            if (t >= 0 && t < TX) {
#pragma unroll
                                for (int co = 0; co < Cout; co++) {
#pragma unroll
                                    for (int kz = 0; kz < K; kz++) {
                                        float w = sw[((((co * Cin + ci) * K + kw) * K + kx) * K + ky) * K + kz];
#pragma unroll
                                        for (int z = 0; z < Sout; z++)
                                            acc[(co * TX + t) * Sout + z] +=
                                                r[j][z + kz] * w;
                                    }
                                }
                            }
                        }
                    }
                }
            }
        }
    }

#pragma unroll
    for (int co = 0; co < Cout; co++) {
#pragma unroll
        for (int t = 0; t < TX; t++) {
            float* op = out +
                (size_t)((((b * Cout + co) * Sout + w0) * Sout + (x0 + t)) * Sout + y0) * PSout;
            float rr[Sout];
#pragma unroll
            for (int z = 0; z < Sout; z++)
                rr[z] = fmaxf(acc[(co * TX + t) * Sout + z], 0.0f);
            store_row<Sout, 4>(op, rr);
        }
    }
}

// ---------------------------------------------------------------------------
// Head: per-sample block. dense 1280->33 (ReLU), dense 33->2, softmax.
// ---------------------------------------------------------------------------
__global__ void __launch_bounds__(64)
head_kernel(const float* __restrict__ h,
            const float* __restrict__ dw1, const float* __restrict__ db1,
            const float* __restrict__ dw2, const float* __restrict__ db2,
            float* __restrict__ out)
{
    int b = blockIdx.x;
    __shared__ float sh[1280];
    __shared__ float s1[33];

    for (int i = threadIdx.x; i < 1280; i += blockDim.x)
        sh[i] = h[b * 1280 + i];
    __syncthreads();

    int j = threadIdx.x;
    if (j < 33) {
        float s = db1[j];
        const float* wr = dw1 + j * 1280;
#pragma unroll 4
        for (int i = 0; i < 1280; i++) s += wr[i] * sh[i];
        s1[j] = fmaxf(s, 0.0f);
    }
    __syncthreads();

    if (threadIdx.x == 0) {
        float l0 = db2[0], l1 = db2[1];
        for (int jj = 0; jj < 33; jj++) {
            l0 += dw2[jj] * s1[jj];
            l1 += dw2[33 + jj] * s1[jj];
        }
        float m  = fmaxf(l0, l1);
        float e0 = expf(l0 - m);
        float e1 = expf(l1 - m);
        float inv = 1.0f / (e0 + e1);
        out[b * 2 + 0] = e0 * inv;
        out[b * 2 + 1] = e1 * inv;
    }
}

static inline int cdiv(int a, int b) { return (a + b - 1) / b; }

extern "C" void kernel_launch(void* const* d_in, const int* in_sizes, int n_in,
                              void* d_out, int out_size)
{
    const float* x   = (const float*)d_in[0];
    const float* w1  = (const float*)d_in[1];
    const float* b1  = (const float*)d_in[2];
    const float* w2  = (const float*)d_in[3];
    const float* b2  = (const float*)d_in[4];
    const float* w3  = (const float*)d_in[5];
    const float* b3  = (const float*)d_in[6];
    const float* w4  = (const float*)d_in[7];
    const float* b4  = (const float*)d_in[8];
    const float* w5  = (const float*)d_in[9];
    const float* b5  = (const float*)d_in[10];
    const float* dw1 = (const float*)d_in[11];
    const float* db1 = (const float*)d_in[12];
    const float* dw2 = (const float*)d_in[13];
    const float* db2 = (const float*)d_in[14];
    float* out = (float*)d_out;

    float *h1, *h2, *h3, *h4, *h5;
    cudaGetSymbolAddress((void**)&h1, g_h1);
    cudaGetSymbolAddress((void**)&h2, g_h2);
    cudaGetSymbolAddress((void**)&h3, g_h3);
    cudaGetSymbolAddress((void**)&h4, g_h4);
    cudaGetSymbolAddress((void**)&h5, g_h5);

    const int T = 128;

    // conv1: 1->3, 18->15, k=4. float2 in (x stride 18), out h1 stride 16.
    conv4d_relu_kernel<1, 3, 18, 4, 1, 18, 16, 2, 4, 0>
        <<<cdiv(BATCH * 15 * 15 * 15, T), T>>>(x, w1, b1, h1);
    // conv2: 3->3, 15->12, k=4. x-tiled TX=2 kernel (this round's change).
    {
        int threads = BATCH * 12 * 6 * 12;
        conv2_tx2_kernel<<<cdiv(threads, T), T>>>(h1, w2, b2, h2);
    }
    // conv3: 3->4, 12->9, k=4. float4 reads h2 (stride 12), out h3 stride 12.
    conv4d_relu_kernel<3, 4, 12, 4, 1, 12, 12, 4, 4, 1>
        <<<cdiv(BATCH * 9 * 9 * 9, T), T>>>(h2, w3, b3, h3);
    // conv4: 4->5, 9->6, k=4. float4 reads h3 (stride 12), co split x2,
    // out h4 stride 8.
    conv4d_relu_kernel<4, 5, 9, 4, 2, 12, 8, 4, 4, 1>
        <<<cdiv(BATCH * 6 * 6 * 6 * 2, T), T>>>(h3, w4, b4, h4);
    // conv5: 5->5, 6->4, k=3. float4 reads h4 (stride 8), co split x5, out exact.
    conv4d_relu_kernel<5, 5, 6, 3, 5, 8, 4, 4, 4, 1>
        <<<cdiv(BATCH * 4 * 4 * 4 * 5, T), T>>>(h4, w5, b5, h5);
    // head
    head_kernel<<<BATCH, 64>>>(h5, dw1, db1, dw2, db2, out);
}